// round 1
// baseline (speedup 1.0000x reference)
#include <cuda_runtime.h>
#include <cstdint>

#define FULL 0xFFFFFFFFu

// Shapes (fixed by the problem)
// B=512, L=64 nodes, NE=128 edges, D=128, V=200000
constexpr int Bb = 512;
constexpr int Ll = 64;
constexpr int NEe = 128;
constexpr int Dd = 128;
constexpr float ALPHA = 0.2f;

// Precomputed attention-projection vectors (tiny):
//  u1 = w2 @ a[128:256]   (for e1)
//  u2 = w2 @ a2[0:128]    (node part of e2)
//  u3 = w3 @ a2[128:256]  (edge part of e2)
//  c1 = q . a[0:128]
__device__ float g_u1[2][128];
__device__ float g_u2[2][128];
__device__ float g_u3[2][128];
__device__ float g_c1[2];

__global__ void precompute_kernel(
    const float* __restrict__ w2a, const float* __restrict__ w3a,
    const float* __restrict__ qa,  const float* __restrict__ aa,
    const float* __restrict__ a2a,
    const float* __restrict__ w2b, const float* __restrict__ w3b,
    const float* __restrict__ qb,  const float* __restrict__ ab,
    const float* __restrict__ a2b)
{
    int layer = threadIdx.x >> 7;
    int k = threadIdx.x & 127;
    const float* w2 = layer ? w2b : w2a;
    const float* w3 = layer ? w3b : w3a;
    const float* q  = layer ? qb  : qa;
    const float* a  = layer ? ab  : aa;
    const float* a2 = layer ? a2b : a2a;
    float u1 = 0.f, u2 = 0.f, u3 = 0.f;
    #pragma unroll 4
    for (int c = 0; c < 128; c++) {
        float w2v = w2[k * 128 + c];
        u1 += w2v * a[128 + c];
        u2 += w2v * a2[c];
        u3 += w3[k * 128 + c] * a2[128 + c];
    }
    g_u1[layer][k] = u1;
    g_u2[layer][k] = u2;
    g_u3[layer][k] = u3;
    __shared__ float red[256];
    red[threadIdx.x] = q[k] * a[k];
    __syncthreads();
    if (k == 0) {
        float s = 0.f;
        for (int i = 0; i < 128; i++) s += red[layer * 128 + i];
        g_c1[layer] = s;
    }
}

// Shared memory layout (floats):
//  x      [64*128]  = 8192
//  resid  [64*128]  = 8192
//  xtb    [64*128]  = 8192
//  edge   [128*128] = 16384
//  e1v    [64]
//  s2     [64]
//  f2     [128]
//  wt     [8*128]   = 1024 (per-warp softmax weight scratch)
//  emask  [128] u64 = 256 floats
//  nmask  [64*2]u64 = 256 floats
constexpr int SMEM_FLOATS = 8192 * 3 + 16384 + 64 + 64 + 128 + 1024 + 256 + 256;
constexpr int SMEM_BYTES = SMEM_FLOATS * 4;

__global__ __launch_bounds__(256, 1) void session_kernel(
    const int*   __restrict__ inputs,
    const float* __restrict__ HT,
    const float* __restrict__ emb,
    const float* __restrict__ emb2,
    const float* __restrict__ g2w,
    float*       __restrict__ out)
{
    extern __shared__ float smem[];
    float* x     = smem;
    float* resid = x + 8192;
    float* xtb   = resid + 8192;
    float* edge  = xtb + 8192;
    float* e1v   = edge + 16384;
    float* s2    = e1v + 64;
    float* f2    = s2 + 64;
    float* wt    = f2 + 128;
    unsigned long long* emask = (unsigned long long*)(wt + 1024);
    unsigned long long* nmask = emask + 128;

    const int tid  = threadIdx.x;
    const int warp = tid >> 5;
    const int lane = tid & 31;
    const int b    = blockIdx.x;
    const size_t BLD = (size_t)Bb * Ll * Dd;

    // ---- Phase 0: gathers + incidence bitmasks ----
    for (int j = warp; j < Ll; j += 8) {
        int tok = inputs[b * Ll + j];
        float4 v = ((const float4*)(emb + (size_t)tok * Dd))[lane];
        ((float4*)(x + j * Dd))[lane] = v;
        ((float4*)(resid + j * Dd))[lane] = v;
        float4 v2 = ((const float4*)(emb2 + (size_t)tok * Dd))[lane];
        ((float4*)(out + 2 * BLD + ((size_t)b * Ll + j) * Dd))[lane] = v2;
    }
    for (int e = warp; e < NEe; e += 8) {
        const float* row = HT + ((size_t)b * NEe + e) * Ll;
        unsigned lo = __ballot_sync(FULL, row[lane] > 0.f);
        unsigned hi = __ballot_sync(FULL, row[lane + 32] > 0.f);
        if (lane == 0)
            emask[e] = (unsigned long long)lo | ((unsigned long long)hi << 32);
    }
    __syncthreads();
    if (tid < Ll) {
        unsigned long long m0 = 0, m1 = 0;
        #pragma unroll 4
        for (int e = 0; e < 64; e++) {
            if ((emask[e] >> tid) & 1ull)      m0 |= 1ull << e;
            if ((emask[e + 64] >> tid) & 1ull) m1 |= 1ull << e;
        }
        nmask[2 * tid] = m0;
        nmask[2 * tid + 1] = m1;
    }
    __syncthreads();

    float* wts = wt + warp * 128;

    for (int layer = 0; layer < 2; layer++) {
        const float* xt = x;
        // ---- Step A (layer 1 only): xt = x @ g2_w ----
        if (layer == 1) {
            float4 acc[8];
            #pragma unroll
            for (int r = 0; r < 8; r++) acc[r] = make_float4(0.f, 0.f, 0.f, 0.f);
            for (int k = 0; k < 128; k++) {
                float4 wr = ((const float4*)(g2w + k * 128))[lane];
                #pragma unroll
                for (int r = 0; r < 8; r++) {
                    float xv = x[(warp + 8 * r) * 128 + k];
                    acc[r].x += xv * wr.x; acc[r].y += xv * wr.y;
                    acc[r].z += xv * wr.z; acc[r].w += xv * wr.w;
                }
            }
            #pragma unroll
            for (int r = 0; r < 8; r++)
                ((float4*)(xtb + (warp + 8 * r) * 128))[lane] = acc[r];
            xt = xtb;
            __syncthreads();
        }

        // ---- Step B: e1[j], s2[j] via precomputed vectors ----
        const float c1 = g_c1[layer];
        const float4* u1v4 = (const float4*)g_u1[layer];
        const float4* u2v4 = (const float4*)g_u2[layer];
        for (int j = warp; j < Ll; j += 8) {
            float4 xv = ((float4*)(x + j * 128))[lane];
            float4 u1v = u1v4[lane], u2v = u2v4[lane];
            float p1 = xv.x * u1v.x + xv.y * u1v.y + xv.z * u1v.z + xv.w * u1v.w;
            float p2 = xv.x * u2v.x + xv.y * u2v.y + xv.z * u2v.z + xv.w * u2v.w;
            #pragma unroll
            for (int off = 16; off; off >>= 1) {
                p1 += __shfl_xor_sync(FULL, p1, off);
                p2 += __shfl_xor_sync(FULL, p2, off);
            }
            if (lane == 0) {
                float e = c1 + p1;
                e1v[j] = e > 0.f ? e : ALPHA * e;
                s2[j] = p2;
            }
        }
        __syncthreads();

        // ---- Step C: edge softmax over member nodes + edge = att @ xt ----
        const float4* u3v4 = (const float4*)g_u3[layer];
        for (int e = warp; e < NEe; e += 8) {
            unsigned long long m = emask[e];
            float v0 = ((m >> lane) & 1ull) ? e1v[lane] : -1e30f;
            float v1 = ((m >> (lane + 32)) & 1ull) ? e1v[lane + 32] : -1e30f;
            float mx = fmaxf(v0, v1);
            #pragma unroll
            for (int off = 16; off; off >>= 1)
                mx = fmaxf(mx, __shfl_xor_sync(FULL, mx, off));
            unsigned long long mm;
            float w0, w1;
            if (m == 0ull) {
                // empty hyperedge: reference softmax over all-NEG -> uniform
                w0 = w1 = 1.f / 64.f;
                mm = ~0ull;
            } else {
                w0 = ((m >> lane) & 1ull) ? __expf(v0 - mx) : 0.f;
                w1 = ((m >> (lane + 32)) & 1ull) ? __expf(v1 - mx) : 0.f;
                float s = w0 + w1;
                #pragma unroll
                for (int off = 16; off; off >>= 1)
                    s += __shfl_xor_sync(FULL, s, off);
                float inv = 1.f / s;
                w0 *= inv; w1 *= inv;
                mm = m;
            }
            wts[lane] = w0;
            wts[lane + 32] = w1;
            __syncwarp();
            float4 acc = make_float4(0.f, 0.f, 0.f, 0.f);
            while (mm) {
                int j = __ffsll(mm) - 1;
                mm &= mm - 1;
                float wj = wts[j];
                float4 xv = ((const float4*)(xt + j * 128))[lane];
                acc.x += wj * xv.x; acc.y += wj * xv.y;
                acc.z += wj * xv.z; acc.w += wj * xv.w;
            }
            ((float4*)(edge + e * 128))[lane] = acc;
            // f2[e] = edge[e] . u3
            float4 u3v = u3v4[lane];
            float p = acc.x * u3v.x + acc.y * u3v.y + acc.z * u3v.z + acc.w * u3v.w;
            #pragma unroll
            for (int off = 16; off; off >>= 1)
                p += __shfl_xor_sync(FULL, p, off);
            if (lane == 0) f2[e] = p;
            __syncwarp();
        }
        __syncthreads();

        // ---- Step D: node softmax over member edges + node = att @ edge + resid ----
        for (int j = warp; j < Ll; j += 8) {
            unsigned long long m0 = nmask[2 * j], m1 = nmask[2 * j + 1];
            float ss = s2[j];
            int   ei[4] = { lane, lane + 32, lane + 64, lane + 96 };
            bool  bt[4] = { (bool)((m0 >> lane) & 1ull), (bool)((m0 >> (lane + 32)) & 1ull),
                            (bool)((m1 >> lane) & 1ull), (bool)((m1 >> (lane + 32)) & 1ull) };
            float vv[4];
            #pragma unroll
            for (int t = 0; t < 4; t++) {
                float vt = ss + f2[ei[t]];
                vt = vt > 0.f ? vt : ALPHA * vt;
                vv[t] = bt[t] ? vt : -1e30f;
            }
            float mx = fmaxf(fmaxf(vv[0], vv[1]), fmaxf(vv[2], vv[3]));
            #pragma unroll
            for (int off = 16; off; off >>= 1)
                mx = fmaxf(mx, __shfl_xor_sync(FULL, mx, off));
            unsigned long long mm0, mm1;
            float w[4];
            if ((m0 | m1) == 0ull) {
                w[0] = w[1] = w[2] = w[3] = 1.f / 128.f;
                mm0 = mm1 = ~0ull;
            } else {
                float s = 0.f;
                #pragma unroll
                for (int t = 0; t < 4; t++) {
                    w[t] = bt[t] ? __expf(vv[t] - mx) : 0.f;
                    s += w[t];
                }
                #pragma unroll
                for (int off = 16; off; off >>= 1)
                    s += __shfl_xor_sync(FULL, s, off);
                float inv = 1.f / s;
                #pragma unroll
                for (int t = 0; t < 4; t++) w[t] *= inv;
                mm0 = m0; mm1 = m1;
            }
            wts[lane] = w[0]; wts[lane + 32] = w[1];
            wts[lane + 64] = w[2]; wts[lane + 96] = w[3];
            __syncwarp();
            float4 acc = make_float4(0.f, 0.f, 0.f, 0.f);
            while (mm0) {
                int e = __ffsll(mm0) - 1;
                mm0 &= mm0 - 1;
                float we = wts[e];
                float4 ev = ((const float4*)(edge + e * 128))[lane];
                acc.x += we * ev.x; acc.y += we * ev.y;
                acc.z += we * ev.z; acc.w += we * ev.w;
            }
            while (mm1) {
                int e = __ffsll(mm1) - 1;
                mm1 &= mm1 - 1;
                float we = wts[e + 64];
                float4 ev = ((const float4*)(edge + (e + 64) * 128))[lane];
                acc.x += we * ev.x; acc.y += we * ev.y;
                acc.z += we * ev.z; acc.w += we * ev.w;
            }
            float4 rv = ((float4*)(resid + j * 128))[lane];
            acc.x += rv.x; acc.y += rv.y; acc.z += rv.z; acc.w += rv.w;
            ((float4*)(x + j * 128))[lane] = acc;
        }
        __syncthreads();
    }

    // ---- Output: (x, x, nodes2) concatenated ----
    for (int j = warp; j < Ll; j += 8) {
        float4 v = ((float4*)(x + j * 128))[lane];
        ((float4*)(out + ((size_t)b * Ll + j) * Dd))[lane] = v;
        ((float4*)(out + BLD + ((size_t)b * Ll + j) * Dd))[lane] = v;
    }
}

extern "C" void kernel_launch(void* const* d_in, const int* in_sizes, int n_in,
                              void* d_out, int out_size)
{
    const int*   inputs = (const int*)d_in[0];
    const float* HT     = (const float*)d_in[1];
    // d_in[2]=G, d_in[3]=EG unused
    const float* emb    = (const float*)d_in[4];
    const float* emb2   = (const float*)d_in[5];
    const float* g1_w2  = (const float*)d_in[6];
    const float* g1_w3  = (const float*)d_in[7];
    const float* g1_q   = (const float*)d_in[8];
    const float* g1_a   = (const float*)d_in[9];
    const float* g1_a2  = (const float*)d_in[10];
    const float* g2_w   = (const float*)d_in[11];
    const float* g2_w2  = (const float*)d_in[12];
    const float* g2_w3  = (const float*)d_in[13];
    const float* g2_q   = (const float*)d_in[14];
    const float* g2_a   = (const float*)d_in[15];
    const float* g2_a2  = (const float*)d_in[16];
    float* out = (float*)d_out;

    cudaFuncSetAttribute(session_kernel,
                         cudaFuncAttributeMaxDynamicSharedMemorySize, SMEM_BYTES);

    precompute_kernel<<<1, 256>>>(g1_w2, g1_w3, g1_q, g1_a, g1_a2,
                                  g2_w2, g2_w3, g2_q, g2_a, g2_a2);
    session_kernel<<<Bb, 256, SMEM_BYTES>>>(inputs, HT, emb, emb2, g2_w, out);
}

// round 2
// speedup vs baseline: 2.0507x; 2.0507x over previous
#include <cuda_runtime.h>
#include <cstdint>

#define FULL 0xFFFFFFFFu

constexpr int Bb = 512;
constexpr float ALPHA = 0.2f;

__device__ float g_u1[2][128];
__device__ float g_u2[2][128];
__device__ float g_u3[2][128];
__device__ float g_c1[2];

__global__ void precompute_kernel(
    const float* __restrict__ w2a, const float* __restrict__ w3a,
    const float* __restrict__ qa,  const float* __restrict__ aa,
    const float* __restrict__ a2a,
    const float* __restrict__ w2b, const float* __restrict__ w3b,
    const float* __restrict__ qb,  const float* __restrict__ ab,
    const float* __restrict__ a2b)
{
    int layer = threadIdx.x >> 7;
    int k = threadIdx.x & 127;
    const float* w2 = layer ? w2b : w2a;
    const float* w3 = layer ? w3b : w3a;
    const float* q  = layer ? qb  : qa;
    const float* a  = layer ? ab  : aa;
    const float* a2 = layer ? a2b : a2a;
    float u1 = 0.f, u2 = 0.f, u3 = 0.f;
    #pragma unroll 4
    for (int c = 0; c < 128; c++) {
        float w2v = w2[k * 128 + c];
        u1 += w2v * a[128 + c];
        u2 += w2v * a2[c];
        u3 += w3[k * 128 + c] * a2[128 + c];
    }
    g_u1[layer][k] = u1;
    g_u2[layer][k] = u2;
    g_u3[layer][k] = u3;
    __shared__ float red[256];
    red[threadIdx.x] = q[k] * a[k];
    __syncthreads();
    if (k == 0) {
        float s = 0.f;
        for (int i = 0; i < 128; i++) s += red[layer * 128 + i];
        g_c1[layer] = s;
    }
}

constexpr int SMEM_FLOATS = 8192 * 3 + 16384 + 64 + 64 + 128 + 2048 + 256 + 256
                          + 1536 + 1024 + 32 + 128 + 64;
constexpr int SMEM_BYTES = SMEM_FLOATS * 4;

__global__ __launch_bounds__(512, 1) void session_kernel(
    const int*   __restrict__ inputs,
    const float* __restrict__ HT,
    const float* __restrict__ emb,
    const float* __restrict__ emb2,
    const float* __restrict__ g2w,
    float*       __restrict__ out)
{
    extern __shared__ float smem[];
    float* x     = smem;
    float* resid = x + 8192;
    float* xtb   = resid + 8192;
    float* edge  = xtb + 8192;
    float* e1v   = edge + 16384;
    float* s2    = e1v + 64;
    float* f2    = s2 + 64;
    float* wtc   = f2 + 128;
    unsigned long long* emask = (unsigned long long*)(wtc + 2048);
    unsigned long long* nmask = emask + 128;
    uint8_t* elist  = (uint8_t*)(nmask + 128);
    uint8_t* nlist  = elist + 128 * 48;
    uint8_t* idlist = nlist + 64 * 64;
    int* ecnt = (int*)(idlist + 128);
    int* ncnt = ecnt + 128;

    const int tid  = threadIdx.x;
    const int warp = tid >> 5;
    const int lane = tid & 31;
    const int b    = blockIdx.x;
    const size_t BLD = (size_t)Bb * 64 * 128;

    for (int j = warp; j < 64; j += 16) {
        int tok = inputs[b * 64 + j];
        float4 v = ((const float4*)(emb + (size_t)tok * 128))[lane];
        ((float4*)(x + j * 128))[lane] = v;
        ((float4*)(resid + j * 128))[lane] = v;
        float4 v2 = ((const float4*)(emb2 + (size_t)tok * 128))[lane];
        ((float4*)(out + 2 * BLD + ((size_t)b * 64 + j) * 128))[lane] = v2;
    }
    for (int e = warp; e < 128; e += 16) {
        const float* row = HT + ((size_t)b * 128 + e) * 64;
        unsigned lo = __ballot_sync(FULL, row[lane] > 0.f);
        unsigned hi = __ballot_sync(FULL, row[lane + 32] > 0.f);
        if (lane == 0)
            emask[e] = (unsigned long long)lo | ((unsigned long long)hi << 32);
    }
    if (tid < 128) idlist[tid] = (uint8_t)tid;
    __syncthreads();
    if (tid < 64) {
        unsigned long long m0 = 0, m1 = 0;
        #pragma unroll 4
        for (int e = 0; e < 64; e++) {
            m0 |= ((emask[e] >> tid) & 1ull) << e;
            m1 |= ((emask[e + 64] >> tid) & 1ull) << e;
        }
        nmask[2 * tid] = m0;
        nmask[2 * tid + 1] = m1;
    } else if (tid < 192) {
        int e = tid - 64;
        unsigned long long m = emask[e];
        int c = 0;
        uint8_t* l = elist + e * 48;
        while (m) { int j = __ffsll(m) - 1; m &= m - 1; l[c++] = (uint8_t)j; }
        ecnt[e] = c;
    }
    __syncthreads();
    if (tid < 64) {
        unsigned long long m0 = nmask[2 * tid], m1 = nmask[2 * tid + 1];
        int c = 0;
        uint8_t* l = nlist + tid * 64;
        while (m0) { int e = __ffsll(m0) - 1; m0 &= m0 - 1; l[c++] = (uint8_t)e; }
        while (m1) { int e = __ffsll(m1) - 1; m1 &= m1 - 1; l[c++] = (uint8_t)(e + 64); }
        ncnt[tid] = c;
    }
    __syncthreads();

    float* w = wtc + warp * 128;

    for (int layer = 0; layer < 2; layer++) {
        const float* xt = x;
        if (layer == 1) {
            float4 acc[4];
            #pragma unroll
            for (int r = 0; r < 4; r++) acc[r] = make_float4(0.f, 0.f, 0.f, 0.f);
            const float4* w4 = (const float4*)g2w;
            for (int k4 = 0; k4 < 32; k4++) {
                float4 xv[4];
                #pragma unroll
                for (int r = 0; r < 4; r++)
                    xv[r] = ((const float4*)(x + (warp + 16 * r) * 128))[k4];
                #pragma unroll
                for (int kk = 0; kk < 4; kk++) {
                    float4 wr = w4[(k4 * 4 + kk) * 32 + lane];
                    #pragma unroll
                    for (int r = 0; r < 4; r++) {
                        float xs = ((const float*)&xv[r])[kk];
                        acc[r].x += xs * wr.x; acc[r].y += xs * wr.y;
                        acc[r].z += xs * wr.z; acc[r].w += xs * wr.w;
                    }
                }
            }
            #pragma unroll
            for (int r = 0; r < 4; r++)
                ((float4*)(xtb + (warp + 16 * r) * 128))[lane] = acc[r];
            xt = xtb;
            __syncthreads();
        }

        const float  c1   = g_c1[layer];
        const float4* u1v4 = (const float4*)g_u1[layer];
        const float4* u2v4 = (const float4*)g_u2[layer];
        const float4* u3v4 = (const float4*)g_u3[layer];
        for (int j = warp; j < 64; j += 16) {
            float4 xv = ((const float4*)(x + j * 128))[lane];
            float4 u1v = u1v4[lane], u2v = u2v4[lane];
            float p1 = xv.x * u1v.x + xv.y * u1v.y + xv.z * u1v.z + xv.w * u1v.w;
            float p2 = xv.x * u2v.x + xv.y * u2v.y + xv.z * u2v.z + xv.w * u2v.w;
            #pragma unroll
            for (int off = 16; off; off >>= 1) {
                p1 += __shfl_xor_sync(FULL, p1, off);
                p2 += __shfl_xor_sync(FULL, p2, off);
            }
            if (lane == 0) {
                float e = c1 + p1;
                e1v[j] = e > 0.f ? e : ALPHA * e;
                s2[j] = p2;
            }
        }
        __syncthreads();

        const float4* xt4 = (const float4*)xt;
        for (int e = warp; e < 128; e += 16) {
            unsigned long long m = emask[e];
            int cnt;
            const uint8_t* list;
            __syncwarp();
            if (m == 0ull) {
                w[lane] = 1.f / 64.f;
                w[lane + 32] = 1.f / 64.f;
                list = idlist; cnt = 64;
            } else {
                cnt = ecnt[e]; list = elist + e * 48;
                bool b0 = (m >> lane) & 1ull, b1 = (m >> (lane + 32)) & 1ull;
                float v0 = b0 ? e1v[lane] : -1e30f;
                float v1 = b1 ? e1v[lane + 32] : -1e30f;
                float mx = fmaxf(v0, v1);
                #pragma unroll
                for (int off = 16; off; off >>= 1)
                    mx = fmaxf(mx, __shfl_xor_sync(FULL, mx, off));
                float w0 = b0 ? __expf(v0 - mx) : 0.f;
                float w1 = b1 ? __expf(v1 - mx) : 0.f;
                float s = w0 + w1;
                #pragma unroll
                for (int off = 16; off; off >>= 1)
                    s += __shfl_xor_sync(FULL, s, off);
                float inv = 1.f / s;
                if (b0) w[__popcll(m & ((1ull << lane) - 1))] = w0 * inv;
                if (b1) w[__popcll(m & ((1ull << (lane + 32)) - 1))] = w1 * inv;
            }
            __syncwarp();
            float4 a0 = make_float4(0.f, 0.f, 0.f, 0.f);
            float4 a1 = make_float4(0.f, 0.f, 0.f, 0.f);
            int i = 0;
            for (; i + 4 <= cnt; i += 4) {
                uchar4 j4 = *(const uchar4*)(list + i);
                float4 wv = *(const float4*)(w + i);
                float4 v0 = xt4[j4.x * 32 + lane];
                float4 v1 = xt4[j4.y * 32 + lane];
                float4 v2 = xt4[j4.z * 32 + lane];
                float4 v3 = xt4[j4.w * 32 + lane];
                a0.x += wv.x * v0.x; a0.y += wv.x * v0.y; a0.z += wv.x * v0.z; a0.w += wv.x * v0.w;
                a1.x += wv.y * v1.x; a1.y += wv.y * v1.y; a1.z += wv.y * v1.z; a1.w += wv.y * v1.w;
                a0.x += wv.z * v2.x; a0.y += wv.z * v2.y; a0.z += wv.z * v2.z; a0.w += wv.z * v2.w;
                a1.x += wv.w * v3.x; a1.y += wv.w * v3.y; a1.z += wv.w * v3.z; a1.w += wv.w * v3.w;
            }
            for (; i < cnt; i++) {
                int j = list[i];
                float wj = w[i];
                float4 v = xt4[j * 32 + lane];
                a0.x += wj * v.x; a0.y += wj * v.y; a0.z += wj * v.z; a0.w += wj * v.w;
            }
            float4 acc = make_float4(a0.x + a1.x, a0.y + a1.y, a0.z + a1.z, a0.w + a1.w);
            ((float4*)edge)[e * 32 + lane] = acc;
            float4 u3v = u3v4[lane];
            float p = acc.x * u3v.x + acc.y * u3v.y + acc.z * u3v.z + acc.w * u3v.w;
            #pragma unroll
            for (int off = 16; off; off >>= 1)
                p += __shfl_xor_sync(FULL, p, off);
            if (lane == 0) f2[e] = p;
        }
        __syncthreads();

        const float4* edge4 = (const float4*)edge;
        for (int j = warp; j < 64; j += 16) {
            unsigned long long m0 = nmask[2 * j], m1 = nmask[2 * j + 1];
            float ss = s2[j];
            int cnt;
            const uint8_t* list;
            __syncwarp();
            if ((m0 | m1) == 0ull) {
                w[lane] = w[lane + 32] = w[lane + 64] = w[lane + 96] = 1.f / 128.f;
                list = idlist; cnt = 128;
            } else {
                cnt = ncnt[j]; list = nlist + j * 64;
                bool b0 = (m0 >> lane) & 1ull, b1 = (m0 >> (lane + 32)) & 1ull;
                bool b2 = (m1 >> lane) & 1ull, b3 = (m1 >> (lane + 32)) & 1ull;
                float t0 = ss + f2[lane];       t0 = t0 > 0.f ? t0 : ALPHA * t0;
                float t1 = ss + f2[lane + 32];  t1 = t1 > 0.f ? t1 : ALPHA * t1;
                float t2 = ss + f2[lane + 64];  t2 = t2 > 0.f ? t2 : ALPHA * t2;
                float t3 = ss + f2[lane + 96];  t3 = t3 > 0.f ? t3 : ALPHA * t3;
                float v0 = b0 ? t0 : -1e30f;
                float v1 = b1 ? t1 : -1e30f;
                float v2 = b2 ? t2 : -1e30f;
                float v3 = b3 ? t3 : -1e30f;
                float mx = fmaxf(fmaxf(v0, v1), fmaxf(v2, v3));
                #pragma unroll
                for (int off = 16; off; off >>= 1)
                    mx = fmaxf(mx, __shfl_xor_sync(FULL, mx, off));
                float w0 = b0 ? __expf(v0 - mx) : 0.f;
                float w1 = b1 ? __expf(v1 - mx) : 0.f;
                float w2 = b2 ? __expf(v2 - mx) : 0.f;
                float w3 = b3 ? __expf(v3 - mx) : 0.f;
                float s = w0 + w1 + w2 + w3;
                #pragma unroll
                for (int off = 16; off; off >>= 1)
                    s += __shfl_xor_sync(FULL, s, off);
                float inv = 1.f / s;
                int base1 = __popcll(m0);
                if (b0) w[__popcll(m0 & ((1ull << lane) - 1))] = w0 * inv;
                if (b1) w[__popcll(m0 & ((1ull << (lane + 32)) - 1))] = w1 * inv;
                if (b2) w[base1 + __popcll(m1 & ((1ull << lane) - 1))] = w2 * inv;
                if (b3) w[base1 + __popcll(m1 & ((1ull << (lane + 32)) - 1))] = w3 * inv;
            }
            __syncwarp();
            float4 a0 = make_float4(0.f, 0.f, 0.f, 0.f);
            float4 a1 = make_float4(0.f, 0.f, 0.f, 0.f);
            int i = 0;
            for (; i + 4 <= cnt; i += 4) {
                uchar4 e4 = *(const uchar4*)(list + i);
                float4 wv = *(const float4*)(w + i);
                float4 v0 = edge4[e4.x * 32 + lane];
                float4 v1 = edge4[e4.y * 32 + lane];
                float4 v2 = edge4[e4.z * 32 + lane];
                float4 v3 = edge4[e4.w * 32 + lane];
                a0.x += wv.x * v0.x; a0.y += wv.x * v0.y; a0.z += wv.x * v0.z; a0.w += wv.x * v0.w;
                a1.x += wv.y * v1.x; a1.y += wv.y * v1.y; a1.z += wv.y * v1.z; a1.w += wv.y * v1.w;
                a0.x += wv.z * v2.x; a0.y += wv.z * v2.y; a0.z += wv.z * v2.z; a0.w += wv.z * v2.w;
                a1.x += wv.w * v3.x; a1.y += wv.w * v3.y; a1.z += wv.w * v3.z; a1.w += wv.w * v3.w;
            }
            for (; i < cnt; i++) {
                int e = list[i];
                float we = w[i];
                float4 v = edge4[e * 32 + lane];
                a0.x += we * v.x; a0.y += we * v.y; a0.z += we * v.z; a0.w += we * v.w;
            }
            float4 rv = ((const float4*)(resid + j * 128))[lane];
            float4 acc = make_float4(a0.x + a1.x + rv.x, a0.y + a1.y + rv.y,
                                     a0.z + a1.z + rv.z, a0.w + a1.w + rv.w);
            ((float4*)(x + j * 128))[lane] = acc;
        }
        __syncthreads();
    }

    for (int j = warp; j < 64; j += 16) {
        float4 v = ((const float4*)(x + j * 128))[lane];
        ((float4*)(out + ((size_t)b * 64 + j) * 128))[lane] = v;
        ((float4*)(out + BLD + ((size_t)b * 64 + j) * 128))[lane] = v;
    }
}

extern "C" void kernel_launch(void* const* d_in, const int* in_sizes, int n_in,
                              void* d_out, int out_size)
{
    const int*   inputs = (const int*)d_in[0];
    const float* HT     = (const float*)d_in[1];
    const float* emb    = (const float*)d_in[4];
    const float* emb2   = (const float*)d_in[5];
    const float* g1_w2  = (const float*)d_in[6];
    const float* g1_w3  = (const float*)d_in[7];
    const float* g1_q   = (const float*)d_in[8];
    const float* g1_a   = (const float*)d_in[9];
    const float* g1_a2  = (const float*)d_in[10];
    const float* g2_w   = (const float*)d_in[11];
    const float* g2_w2  = (const float*)d_in[12];
    const float* g2_w3  = (const float*)d_in[13];
    const float* g2_q   = (const float*)d_in[14];
    const float* g2_a   = (const float*)d_in[15];
    const float* g2_a2  = (const float*)d_in[16];
    float* out = (float*)d_out;

    cudaFuncSetAttribute(session_kernel,
                         cudaFuncAttributeMaxDynamicSharedMemorySize, SMEM_BYTES);

    precompute_kernel<<<1, 256>>>(g1_w2, g1_w3, g1_q, g1_a, g1_a2,
                                  g2_w2, g2_w3, g2_q, g2_a, g2_a2);
    session_kernel<<<Bb, 512, SMEM_BYTES>>>(inputs, HT, emb, emb2, g2_w, out);
}

// round 3
// speedup vs baseline: 2.2002x; 1.0729x over previous
#include <cuda_runtime.h>
#include <cstdint>

#define FULL 0xFFFFFFFFu

constexpr int Bb = 512;
constexpr float ALPHA = 0.2f;

__device__ float g_u1[2][128];
__device__ float g_u2[2][128];
__device__ float g_u3[2][128];
__device__ float g_c1[2];

__global__ void precompute_kernel(
    const float* __restrict__ w2a, const float* __restrict__ w3a,
    const float* __restrict__ qa,  const float* __restrict__ aa,
    const float* __restrict__ a2a,
    const float* __restrict__ w2b, const float* __restrict__ w3b,
    const float* __restrict__ qb,  const float* __restrict__ ab,
    const float* __restrict__ a2b)
{
    int layer = threadIdx.x >> 7;
    int k = threadIdx.x & 127;
    const float* w2 = layer ? w2b : w2a;
    const float* w3 = layer ? w3b : w3a;
    const float* q  = layer ? qb  : qa;
    const float* a  = layer ? ab  : aa;
    const float* a2 = layer ? a2b : a2a;
    float u1 = 0.f, u2 = 0.f, u3 = 0.f;
    #pragma unroll 4
    for (int c = 0; c < 128; c++) {
        float w2v = w2[k * 128 + c];
        u1 += w2v * a[128 + c];
        u2 += w2v * a2[c];
        u3 += w3[k * 128 + c] * a2[128 + c];
    }
    g_u1[layer][k] = u1;
    g_u2[layer][k] = u2;
    g_u3[layer][k] = u3;
    __shared__ float red[256];
    red[threadIdx.x] = q[k] * a[k];
    __syncthreads();
    if (k == 0) {
        float s = 0.f;
        for (int i = 0; i < 128; i++) s += red[layer * 128 + i];
        g_c1[layer] = s;
    }
}

// smem (floats): x 8192 | resid 8192 | xtb 8192 | edge 16384 | e1v 64 | s2 64
// | f2 128 | wtc 32*128=4096 | emask 256 | nmask 256
// | elist16 128*48 u16 = 3072 | nlist16 64*64 u16 = 2048 | idlist16 128 u16 = 64
// | ecnt 128 | ncnt 64
constexpr int SMEM_FLOATS = 8192 * 3 + 16384 + 64 + 64 + 128 + 4096 + 256 + 256
                          + 3072 + 2048 + 64 + 128 + 64;
constexpr int SMEM_BYTES = SMEM_FLOATS * 4;  // 204800 B

__global__ __launch_bounds__(1024, 1) void session_kernel(
    const int*   __restrict__ inputs,
    const float* __restrict__ HT,
    const float* __restrict__ emb,
    const float* __restrict__ emb2,
    const float* __restrict__ g2w,
    float*       __restrict__ out)
{
    extern __shared__ float smem[];
    float* x     = smem;
    float* resid = x + 8192;
    float* xtb   = resid + 8192;
    float* edge  = xtb + 8192;
    float* e1v   = edge + 16384;
    float* s2    = e1v + 64;
    float* f2    = s2 + 64;
    float* wtc   = f2 + 128;
    unsigned long long* emask = (unsigned long long*)(wtc + 4096);
    unsigned long long* nmask = emask + 128;
    uint16_t* elist  = (uint16_t*)(nmask + 128);     // 128*48 entries, val = j*32
    uint16_t* nlist  = elist + 128 * 48;             // 64*64 entries,  val = e*32
    uint16_t* idlist = nlist + 64 * 64;              // 128 entries,    val = i*32
    int* ecnt = (int*)(idlist + 128);
    int* ncnt = ecnt + 128;

    const int tid  = threadIdx.x;
    const int warp = tid >> 5;
    const int lane = tid & 31;
    const int b    = blockIdx.x;
    const size_t BLD = (size_t)Bb * 64 * 128;

    // ---- Phase 0: gathers + masks + pre-scaled index lists ----
    for (int j = warp; j < 64; j += 32) {
        int tok = inputs[b * 64 + j];
        float4 v = ((const float4*)(emb + (size_t)tok * 128))[lane];
        ((float4*)(x + j * 128))[lane] = v;
        ((float4*)(resid + j * 128))[lane] = v;
        float4 v2 = ((const float4*)(emb2 + (size_t)tok * 128))[lane];
        ((float4*)(out + 2 * BLD + ((size_t)b * 64 + j) * 128))[lane] = v2;
    }
    for (int e = warp; e < 128; e += 32) {
        const float* row = HT + ((size_t)b * 128 + e) * 64;
        unsigned lo = __ballot_sync(FULL, row[lane] > 0.f);
        unsigned hi = __ballot_sync(FULL, row[lane + 32] > 0.f);
        if (lane == 0)
            emask[e] = (unsigned long long)lo | ((unsigned long long)hi << 32);
    }
    if (tid < 128) idlist[tid] = (uint16_t)(tid * 32);
    __syncthreads();
    if (tid < 64) {
        unsigned long long m0 = 0, m1 = 0;
        #pragma unroll 4
        for (int e = 0; e < 64; e++) {
            m0 |= ((emask[e] >> tid) & 1ull) << e;
            m1 |= ((emask[e + 64] >> tid) & 1ull) << e;
        }
        nmask[2 * tid] = m0;
        nmask[2 * tid + 1] = m1;
    } else if (tid < 192) {
        int e = tid - 64;
        unsigned long long m = emask[e];
        int c = 0;
        uint16_t* l = elist + e * 48;
        while (m) { int j = __ffsll(m) - 1; m &= m - 1; l[c++] = (uint16_t)(j * 32); }
        ecnt[e] = c;
    }
    __syncthreads();
    if (tid < 64) {
        unsigned long long m0 = nmask[2 * tid], m1 = nmask[2 * tid + 1];
        int c = 0;
        uint16_t* l = nlist + tid * 64;
        while (m0) { int e = __ffsll(m0) - 1; m0 &= m0 - 1; l[c++] = (uint16_t)(e * 32); }
        while (m1) { int e = __ffsll(m1) - 1; m1 &= m1 - 1; l[c++] = (uint16_t)((e + 64) * 32); }
        ncnt[tid] = c;
    }
    __syncthreads();

    float* w = wtc + warp * 128;

    for (int layer = 0; layer < 2; layer++) {
        const float* xt = x;
        // ---- Step A (layer 1 only): xtb = x @ g2_w, 2 rows per warp ----
        if (layer == 1) {
            float4 acc0 = make_float4(0.f, 0.f, 0.f, 0.f);
            float4 acc1 = make_float4(0.f, 0.f, 0.f, 0.f);
            const float4* w4 = (const float4*)g2w;
            for (int k4 = 0; k4 < 32; k4++) {
                float4 xv0 = ((const float4*)(x + warp * 128))[k4];
                float4 xv1 = ((const float4*)(x + (warp + 32) * 128))[k4];
                #pragma unroll
                for (int kk = 0; kk < 4; kk++) {
                    float4 wr = w4[(k4 * 4 + kk) * 32 + lane];
                    float s0 = ((const float*)&xv0)[kk];
                    float s1 = ((const float*)&xv1)[kk];
                    acc0.x += s0 * wr.x; acc0.y += s0 * wr.y;
                    acc0.z += s0 * wr.z; acc0.w += s0 * wr.w;
                    acc1.x += s1 * wr.x; acc1.y += s1 * wr.y;
                    acc1.z += s1 * wr.z; acc1.w += s1 * wr.w;
                }
            }
            ((float4*)(xtb + warp * 128))[lane] = acc0;
            ((float4*)(xtb + (warp + 32) * 128))[lane] = acc1;
            xt = xtb;
            __syncthreads();
        }

        // ---- Step B: e1[j], s2[j] ----
        const float  c1   = g_c1[layer];
        const float4* u1v4 = (const float4*)g_u1[layer];
        const float4* u2v4 = (const float4*)g_u2[layer];
        const float4* u3v4 = (const float4*)g_u3[layer];
        for (int j = warp; j < 64; j += 32) {
            float4 xv = ((const float4*)(x + j * 128))[lane];
            float4 u1v = u1v4[lane], u2v = u2v4[lane];
            float p1 = xv.x * u1v.x + xv.y * u1v.y + xv.z * u1v.z + xv.w * u1v.w;
            float p2 = xv.x * u2v.x + xv.y * u2v.y + xv.z * u2v.z + xv.w * u2v.w;
            #pragma unroll
            for (int off = 16; off; off >>= 1) {
                p1 += __shfl_xor_sync(FULL, p1, off);
                p2 += __shfl_xor_sync(FULL, p2, off);
            }
            if (lane == 0) {
                float e = c1 + p1;
                e1v[j] = e > 0.f ? e : ALPHA * e;
                s2[j] = p2;
            }
        }
        __syncthreads();

        // ---- Step C: edge softmax + edge = att @ xt + f2 ----
        const float4* xt4 = (const float4*)xt;
        for (int e = warp; e < 128; e += 32) {
            unsigned long long m = emask[e];
            int cnt;
            const uint16_t* list;
            __syncwarp();
            if (m == 0ull) {
                w[lane] = 1.f / 64.f;
                w[lane + 32] = 1.f / 64.f;
                list = idlist; cnt = 64;
            } else {
                cnt = ecnt[e]; list = elist + e * 48;
                bool b0 = (m >> lane) & 1ull, b1 = (m >> (lane + 32)) & 1ull;
                float v0 = b0 ? e1v[lane] : -1e30f;
                float v1 = b1 ? e1v[lane + 32] : -1e30f;
                float mx = fmaxf(v0, v1);
                #pragma unroll
                for (int off = 16; off; off >>= 1)
                    mx = fmaxf(mx, __shfl_xor_sync(FULL, mx, off));
                float w0 = b0 ? __expf(v0 - mx) : 0.f;
                float w1 = b1 ? __expf(v1 - mx) : 0.f;
                float s = w0 + w1;
                #pragma unroll
                for (int off = 16; off; off >>= 1)
                    s += __shfl_xor_sync(FULL, s, off);
                float inv = 1.f / s;
                if (b0) w[__popcll(m & ((1ull << lane) - 1))] = w0 * inv;
                if (b1) w[__popcll(m & ((1ull << (lane + 32)) - 1))] = w1 * inv;
            }
            __syncwarp();
            float4 a0 = make_float4(0.f, 0.f, 0.f, 0.f);
            float4 a1 = make_float4(0.f, 0.f, 0.f, 0.f);
            int i = 0;
            for (; i + 4 <= cnt; i += 4) {
                ushort4 j4 = *(const ushort4*)(list + i);
                float4 wv = *(const float4*)(w + i);
                float4 v0 = xt4[j4.x + lane];
                float4 v1 = xt4[j4.y + lane];
                float4 v2 = xt4[j4.z + lane];
                float4 v3 = xt4[j4.w + lane];
                a0.x += wv.x * v0.x; a0.y += wv.x * v0.y; a0.z += wv.x * v0.z; a0.w += wv.x * v0.w;
                a1.x += wv.y * v1.x; a1.y += wv.y * v1.y; a1.z += wv.y * v1.z; a1.w += wv.y * v1.w;
                a0.x += wv.z * v2.x; a0.y += wv.z * v2.y; a0.z += wv.z * v2.z; a0.w += wv.z * v2.w;
                a1.x += wv.w * v3.x; a1.y += wv.w * v3.y; a1.z += wv.w * v3.z; a1.w += wv.w * v3.w;
            }
            for (; i < cnt; i++) {
                int jo = list[i];
                float wj = w[i];
                float4 v = xt4[jo + lane];
                a0.x += wj * v.x; a0.y += wj * v.y; a0.z += wj * v.z; a0.w += wj * v.w;
            }
            float4 acc = make_float4(a0.x + a1.x, a0.y + a1.y, a0.z + a1.z, a0.w + a1.w);
            ((float4*)edge)[e * 32 + lane] = acc;
            float4 u3v = u3v4[lane];
            float p = acc.x * u3v.x + acc.y * u3v.y + acc.z * u3v.z + acc.w * u3v.w;
            #pragma unroll
            for (int off = 16; off; off >>= 1)
                p += __shfl_xor_sync(FULL, p, off);
            if (lane == 0) f2[e] = p;
        }
        __syncthreads();

        // ---- Step D: node softmax + node = att @ edge + resid ----
        const float4* edge4 = (const float4*)edge;
        for (int j = warp; j < 64; j += 32) {
            unsigned long long m0 = nmask[2 * j], m1 = nmask[2 * j + 1];
            float ss = s2[j];
            int cnt;
            const uint16_t* list;
            __syncwarp();
            if ((m0 | m1) == 0ull) {
                w[lane] = w[lane + 32] = w[lane + 64] = w[lane + 96] = 1.f / 128.f;
                list = idlist; cnt = 128;
            } else {
                cnt = ncnt[j]; list = nlist + j * 64;
                bool b0 = (m0 >> lane) & 1ull, b1 = (m0 >> (lane + 32)) & 1ull;
                bool b2 = (m1 >> lane) & 1ull, b3 = (m1 >> (lane + 32)) & 1ull;
                float t0 = ss + f2[lane];       t0 = t0 > 0.f ? t0 : ALPHA * t0;
                float t1 = ss + f2[lane + 32];  t1 = t1 > 0.f ? t1 : ALPHA * t1;
                float t2 = ss + f2[lane + 64];  t2 = t2 > 0.f ? t2 : ALPHA * t2;
                float t3 = ss + f2[lane + 96];  t3 = t3 > 0.f ? t3 : ALPHA * t3;
                float v0 = b0 ? t0 : -1e30f;
                float v1 = b1 ? t1 : -1e30f;
                float v2 = b2 ? t2 : -1e30f;
                float v3 = b3 ? t3 : -1e30f;
                float mx = fmaxf(fmaxf(v0, v1), fmaxf(v2, v3));
                #pragma unroll
                for (int off = 16; off; off >>= 1)
                    mx = fmaxf(mx, __shfl_xor_sync(FULL, mx, off));
                float w0 = b0 ? __expf(v0 - mx) : 0.f;
                float w1 = b1 ? __expf(v1 - mx) : 0.f;
                float w2 = b2 ? __expf(v2 - mx) : 0.f;
                float w3 = b3 ? __expf(v3 - mx) : 0.f;
                float s = w0 + w1 + w2 + w3;
                #pragma unroll
                for (int off = 16; off; off >>= 1)
                    s += __shfl_xor_sync(FULL, s, off);
                float inv = 1.f / s;
                int base1 = __popcll(m0);
                if (b0) w[__popcll(m0 & ((1ull << lane) - 1))] = w0 * inv;
                if (b1) w[__popcll(m0 & ((1ull << (lane + 32)) - 1))] = w1 * inv;
                if (b2) w[base1 + __popcll(m1 & ((1ull << lane) - 1))] = w2 * inv;
                if (b3) w[base1 + __popcll(m1 & ((1ull << (lane + 32)) - 1))] = w3 * inv;
            }
            __syncwarp();
            float4 a0 = make_float4(0.f, 0.f, 0.f, 0.f);
            float4 a1 = make_float4(0.f, 0.f, 0.f, 0.f);
            int i = 0;
            for (; i + 4 <= cnt; i += 4) {
                ushort4 e4 = *(const ushort4*)(list + i);
                float4 wv = *(const float4*)(w + i);
                float4 v0 = edge4[e4.x + lane];
                float4 v1 = edge4[e4.y + lane];
                float4 v2 = edge4[e4.z + lane];
                float4 v3 = edge4[e4.w + lane];
                a0.x += wv.x * v0.x; a0.y += wv.x * v0.y; a0.z += wv.x * v0.z; a0.w += wv.x * v0.w;
                a1.x += wv.y * v1.x; a1.y += wv.y * v1.y; a1.z += wv.y * v1.z; a1.w += wv.y * v1.w;
                a0.x += wv.z * v2.x; a0.y += wv.z * v2.y; a0.z += wv.z * v2.z; a0.w += wv.z * v2.w;
                a1.x += wv.w * v3.x; a1.y += wv.w * v3.y; a1.z += wv.w * v3.z; a1.w += wv.w * v3.w;
            }
            for (; i < cnt; i++) {
                int eo = list[i];
                float we = w[i];
                float4 v = edge4[eo + lane];
                a0.x += we * v.x; a0.y += we * v.y; a0.z += we * v.z; a0.w += we * v.w;
            }
            float4 rv = ((const float4*)(resid + j * 128))[lane];
            float4 acc = make_float4(a0.x + a1.x + rv.x, a0.y + a1.y + rv.y,
                                     a0.z + a1.z + rv.z, a0.w + a1.w + rv.w);
            ((float4*)(x + j * 128))[lane] = acc;
        }
        __syncthreads();
    }

    // ---- Output: (x, x, nodes2) ----
    for (int j = warp; j < 64; j += 32) {
        float4 v = ((const float4*)(x + j * 128))[lane];
        ((float4*)(out + ((size_t)b * 64 + j) * 128))[lane] = v;
        ((float4*)(out + BLD + ((size_t)b * 64 + j) * 128))[lane] = v;
    }
}

extern "C" void kernel_launch(void* const* d_in, const int* in_sizes, int n_in,
                              void* d_out, int out_size)
{
    const int*   inputs = (const int*)d_in[0];
    const float* HT     = (const float*)d_in[1];
    const float* emb    = (const float*)d_in[4];
    const float* emb2   = (const float*)d_in[5];
    const float* g1_w2  = (const float*)d_in[6];
    const float* g1_w3  = (const float*)d_in[7];
    const float* g1_q   = (const float*)d_in[8];
    const float* g1_a   = (const float*)d_in[9];
    const float* g1_a2  = (const float*)d_in[10];
    const float* g2_w   = (const float*)d_in[11];
    const float* g2_w2  = (const float*)d_in[12];
    const float* g2_w3  = (const float*)d_in[13];
    const float* g2_q   = (const float*)d_in[14];
    const float* g2_a   = (const float*)d_in[15];
    const float* g2_a2  = (const float*)d_in[16];
    float* out = (float*)d_out;

    cudaFuncSetAttribute(session_kernel,
                         cudaFuncAttributeMaxDynamicSharedMemorySize, SMEM_BYTES);

    precompute_kernel<<<1, 256>>>(g1_w2, g1_w3, g1_q, g1_a, g1_a2,
                                  g2_w2, g2_w3, g2_q, g2_a, g2_a2);
    session_kernel<<<Bb, 1024, SMEM_BYTES>>>(inputs, HT, emb, emb2, g2_w, out);
}